// round 2
// baseline (speedup 1.0000x reference)
#include <cuda_runtime.h>
#include <cstdint>

// Shapes: N=128, T=256, E=6, D=10
//   merged   : (128,256,14)  fp32  -- UNUSED
//   y_pred_i : (128,256,6)   fp32
//   y_pred_ij: (128,128,256,6) fp32  (dominant: ~100.7 MB, streamed once)
//   input1   : (128,256,15)  fp32  (err_true = cols 7..12)
//   samples  : (128,10)      fp32
//   labels   : (128,)        int64 -- UNUSED
// Output: scalar fp32 L_sim.

#define NPAIR 128
#define TE    1536   // T*E
#define TE4   384    // TE/4
#define NBLOCKS (128 * 16)

__device__ float    g_second[NPAIR * NPAIR];
__device__ unsigned g_ctr = 0;

// ---------------------------------------------------------------------------
// Fused kernel.
// grid = (j: 128, grp: 16), block = 128 threads (4 warps).
// Phase 1 (all blocks): second[i,j] = sum_{t,e} (yij[i,j,t,e]-yi[j,t,e])^2
//                                     / err[j,t,e]^2 / 15360
//   Each block stages w[j] = (1/15360)/err^2 and y_pred_i[j] in smem,
//   each warp streams 2 rows of yij (fully coalesced float4).
// Phase 2 (last block only, via ticket): L_sim reduction over all (i,j).
// ---------------------------------------------------------------------------
__global__ void __launch_bounds__(128, 12)
fused_kernel(const float* __restrict__ yij,
             const float* __restrict__ yi,
             const float* __restrict__ in1,
             const float* __restrict__ samples,
             float* __restrict__ out)
{
    __shared__ float w_f[TE];
    __shared__ float y_f[TE];
    __shared__ unsigned s_ticket;
    __shared__ float s_part[4];

    const int j   = blockIdx.x;
    const int grp = blockIdx.y;
    const int tid = threadIdx.x;

    // ---- stage weights + y_pred_i[j] into smem -----------------------------
    const float scale = 1.0f / 15360.0f;   // 1/(T*E*10)
    #pragma unroll
    for (int t = tid; t < 256; t += 128) {
        const float* e6 = in1 + (j * 256 + t) * 15 + 7;
        #pragma unroll
        for (int c = 0; c < 6; ++c) {
            float e = e6[c];
            w_f[t * 6 + c] = scale / (e * e);
        }
    }
    {
        const float4* yrow = reinterpret_cast<const float4*>(yi + j * TE);
        float4* y4 = reinterpret_cast<float4*>(y_f);
        #pragma unroll
        for (int x = tid; x < TE4; x += 128) y4[x] = yrow[x];
    }
    __syncthreads();

    // ---- stream 2 rows of yij per warp -------------------------------------
    const int warp = tid >> 5;
    const int lane = tid & 31;
    const int i0   = grp * 8 + warp * 2;

    const float4* w4 = reinterpret_cast<const float4*>(w_f);
    const float4* y4 = reinterpret_cast<const float4*>(y_f);
    const float4* p0 = reinterpret_cast<const float4*>(
        yij + (size_t)(i0 * NPAIR + j) * TE);
    const float4* p1 = reinterpret_cast<const float4*>(
        yij + (size_t)((i0 + 1) * NPAIR + j) * TE);

    float a0 = 0.0f, a1 = 0.0f;
    #pragma unroll
    for (int k = 0; k < 12; ++k) {
        const int x = lane + 32 * k;
        const float4 wv = w4[x];
        const float4 yv = y4[x];
        const float4 g0 = p0[x];
        const float4 g1 = p1[x];
        float d;
        d = g0.x - yv.x; a0 = fmaf(d * d, wv.x, a0);
        d = g0.y - yv.y; a0 = fmaf(d * d, wv.y, a0);
        d = g0.z - yv.z; a0 = fmaf(d * d, wv.z, a0);
        d = g0.w - yv.w; a0 = fmaf(d * d, wv.w, a0);
        d = g1.x - yv.x; a1 = fmaf(d * d, wv.x, a1);
        d = g1.y - yv.y; a1 = fmaf(d * d, wv.y, a1);
        d = g1.z - yv.z; a1 = fmaf(d * d, wv.z, a1);
        d = g1.w - yv.w; a1 = fmaf(d * d, wv.w, a1);
    }
    #pragma unroll
    for (int o = 16; o; o >>= 1) {
        a0 += __shfl_xor_sync(0xFFFFFFFFu, a0, o);
        a1 += __shfl_xor_sync(0xFFFFFFFFu, a1, o);
    }
    if (lane == 0) {
        g_second[i0 * NPAIR + j]       = a0;
        g_second[(i0 + 1) * NPAIR + j] = a1;
        __threadfence();   // make this block's results device-visible
    }
    __syncthreads();       // order all warps' fences before the ticket

    if (tid == 0) s_ticket = atomicAdd(&g_ctr, 1u);
    __syncthreads();
    if (s_ticket != NBLOCKS - 1) return;

    // ---- phase 2: last block computes the final loss ------------------------
    if (tid == 0) g_ctr = 0;   // reset for the next graph replay

    // reuse w_f for samples (128*10 floats = 5 KB)
    for (int x = tid; x < 1280; x += 128) w_f[x] = samples[x];
    __syncthreads();

    const int jj = tid;        // one column per thread
    float sj[10];
    #pragma unroll
    for (int d = 0; d < 10; ++d) sj[d] = w_f[jj * 10 + d];

    float acc = 0.0f;
    #pragma unroll 4
    for (int i = 0; i < NPAIR; ++i) {
        float S = 0.0f;
        #pragma unroll
        for (int d = 0; d < 10; ++d) {
            float df = w_f[i * 10 + d] - sj[d];
            S = fmaf(df, df, S);
        }
        // __ldcg: bypass L1 (results written by other SMs live in L2)
        float sA = __ldcg(&g_second[i * NPAIR + jj]);
        float sB = __ldcg(&g_second[jj * NPAIR + i]);
        acc += fabsf(S * 0.1f - 0.5f * (sA + sB));
    }
    #pragma unroll
    for (int o = 16; o; o >>= 1)
        acc += __shfl_xor_sync(0xFFFFFFFFu, acc, o);
    if (lane == 0) s_part[warp] = acc;
    __syncthreads();
    if (tid == 0)
        out[0] = (s_part[0] + s_part[1] + s_part[2] + s_part[3])
                 * (1.0f / 16384.0f);
}

// ---------------------------------------------------------------------------
extern "C" void kernel_launch(void* const* d_in, const int* in_sizes, int n_in,
                              void* d_out, int out_size)
{
    (void)in_sizes; (void)n_in; (void)out_size;
    const float* yi      = (const float*)d_in[1];
    const float* yij     = (const float*)d_in[2];
    const float* in1     = (const float*)d_in[3];
    const float* samples = (const float*)d_in[4];
    float* out = (float*)d_out;

    dim3 grid(NPAIR, 16);
    fused_kernel<<<grid, 128>>>(yij, yi, in1, samples, out);
}

// round 3
// speedup vs baseline: 1.0751x; 1.0751x over previous
#include <cuda_runtime.h>
#include <cstdint>

// Shapes: N=128, T=256, E=6, D=10
//   merged   : (128,256,14)  fp32  -- UNUSED
//   y_pred_i : (128,256,6)   fp32
//   y_pred_ij: (128,128,256,6) fp32  (dominant: ~100.7 MB, streamed once)
//   input1   : (128,256,15)  fp32  (err_true = cols 7..12)
//   samples  : (128,10)      fp32
//   labels   : (128,)        int64 -- UNUSED
// Output: scalar fp32 L_sim.

#define NPAIR 128
#define TE    1536   // T*E
#define TE4   384    // TE/4
#define NBLOCKS 1024 // 128 j * 8 grp

__device__ float    g_second[NPAIR * NPAIR];
__device__ unsigned g_ctr = 0;

// ---------------------------------------------------------------------------
// Fused kernel.
// grid = (j: 128, grp: 8), block = 256 threads (8 warps).  [R1-proven config]
// Phase 1: second[i,j] = sum_{t,e} (yij-yi)^2 / err^2 / 15360
//   Block stages w[j], y_pred_i[j] in smem; each warp streams 2 rows of yij
//   (24 coalesced float4 loads, NO register cap so ptxas keeps MLP high).
// Phase 2 (last block via ticket): L_sim reduction over all (i,j).
// ---------------------------------------------------------------------------
__global__ void __launch_bounds__(256)
fused_kernel(const float* __restrict__ yij,
             const float* __restrict__ yi,
             const float* __restrict__ in1,
             const float* __restrict__ samples,
             float* __restrict__ out)
{
    __shared__ float w_f[TE];
    __shared__ float y_f[TE];
    __shared__ unsigned s_ticket;
    __shared__ float s_part[8];

    const int j   = blockIdx.x;
    const int grp = blockIdx.y;
    const int tid = threadIdx.x;

    // ---- stage weights + y_pred_i[j] into smem -----------------------------
    const float scale = 1.0f / 15360.0f;   // 1/(T*E*10)
    #pragma unroll
    for (int idx = tid; idx < TE; idx += 256) {
        int t = idx / 6;
        int c = idx - t * 6;
        float e = in1[(j * 256 + t) * 15 + 7 + c];
        w_f[idx] = scale / (e * e);
    }
    {
        const float4* yrow = reinterpret_cast<const float4*>(yi + j * TE);
        float4* y4 = reinterpret_cast<float4*>(y_f);
        #pragma unroll
        for (int x = tid; x < TE4; x += 256) y4[x] = yrow[x];
    }
    __syncthreads();

    // ---- stream 2 rows of yij per warp -------------------------------------
    const int warp = tid >> 5;
    const int lane = tid & 31;
    const int i0   = grp * 16 + warp * 2;

    const float4* w4 = reinterpret_cast<const float4*>(w_f);
    const float4* y4 = reinterpret_cast<const float4*>(y_f);
    const float4* p0 = reinterpret_cast<const float4*>(
        yij + (size_t)(i0 * NPAIR + j) * TE);
    const float4* p1 = reinterpret_cast<const float4*>(
        yij + (size_t)((i0 + 1) * NPAIR + j) * TE);

    float a0 = 0.0f, a1 = 0.0f;
    #pragma unroll
    for (int k = 0; k < 12; ++k) {
        const int x = lane + 32 * k;
        const float4 wv = w4[x];
        const float4 yv = y4[x];
        const float4 g0 = p0[x];
        const float4 g1 = p1[x];
        float d;
        d = g0.x - yv.x; a0 = fmaf(d * d, wv.x, a0);
        d = g0.y - yv.y; a0 = fmaf(d * d, wv.y, a0);
        d = g0.z - yv.z; a0 = fmaf(d * d, wv.z, a0);
        d = g0.w - yv.w; a0 = fmaf(d * d, wv.w, a0);
        d = g1.x - yv.x; a1 = fmaf(d * d, wv.x, a1);
        d = g1.y - yv.y; a1 = fmaf(d * d, wv.y, a1);
        d = g1.z - yv.z; a1 = fmaf(d * d, wv.z, a1);
        d = g1.w - yv.w; a1 = fmaf(d * d, wv.w, a1);
    }
    #pragma unroll
    for (int o = 16; o; o >>= 1) {
        a0 += __shfl_xor_sync(0xFFFFFFFFu, a0, o);
        a1 += __shfl_xor_sync(0xFFFFFFFFu, a1, o);
    }
    if (lane == 0) {
        g_second[i0 * NPAIR + j]       = a0;
        g_second[(i0 + 1) * NPAIR + j] = a1;
        __threadfence();   // make this block's results device-visible
    }
    __syncthreads();       // all warps' fenced stores precede the ticket

    if (tid == 0) s_ticket = atomicAdd(&g_ctr, 1u);
    __syncthreads();
    if (s_ticket != NBLOCKS - 1) return;

    // ---- phase 2: last block computes the final loss ------------------------
    if (tid == 0) g_ctr = 0;   // reset for next graph replay

    // reuse w_f for samples (128*10 floats)
    for (int x = tid; x < 1280; x += 256) w_f[x] = samples[x];
    __syncthreads();

    const int jj   = tid & 127;     // column
    const int half = tid >> 7;      // i-range half: [64*half, 64*half+64)
    float sj[10];
    #pragma unroll
    for (int d = 0; d < 10; ++d) sj[d] = w_f[jj * 10 + d];

    float acc = 0.0f;
    const int ibeg = half * 64;
    #pragma unroll 4
    for (int q = 0; q < 64; ++q) {
        const int i = ibeg + q;
        float S = 0.0f;
        #pragma unroll
        for (int d = 0; d < 10; ++d) {
            float df = w_f[i * 10 + d] - sj[d];
            S = fmaf(df, df, S);
        }
        float sA = __ldcg(&g_second[i * NPAIR + jj]);
        float sB = __ldcg(&g_second[jj * NPAIR + i]);
        acc += fabsf(S * 0.1f - 0.5f * (sA + sB));
    }
    #pragma unroll
    for (int o = 16; o; o >>= 1)
        acc += __shfl_xor_sync(0xFFFFFFFFu, acc, o);
    if (lane == 0) s_part[warp] = acc;
    __syncthreads();
    if (tid == 0) {
        float s = 0.0f;
        #pragma unroll
        for (int wv = 0; wv < 8; ++wv) s += s_part[wv];
        out[0] = s * (1.0f / 16384.0f);
    }
}

// ---------------------------------------------------------------------------
extern "C" void kernel_launch(void* const* d_in, const int* in_sizes, int n_in,
                              void* d_out, int out_size)
{
    (void)in_sizes; (void)n_in; (void)out_size;
    const float* yi      = (const float*)d_in[1];
    const float* yij     = (const float*)d_in[2];
    const float* in1     = (const float*)d_in[3];
    const float* samples = (const float*)d_in[4];
    float* out = (float*)d_out;

    dim3 grid(NPAIR, 8);
    fused_kernel<<<grid, 256>>>(yij, yi, in1, samples, out);
}

// round 4
// speedup vs baseline: 1.1757x; 1.0936x over previous
#include <cuda_runtime.h>
#include <cstdint>

// Shapes: N=128, T=256, E=6, D=10
//   merged   : (128,256,14)  fp32  -- UNUSED
//   y_pred_i : (128,256,6)   fp32
//   y_pred_ij: (128,128,256,6) fp32  (dominant: ~100.7 MB, streamed once)
//   input1   : (128,256,15)  fp32  (err_true = cols 7..12)
//   samples  : (128,10)      fp32
//   labels   : (128,)        int64 -- UNUSED
// Output: scalar fp32 L_sim.

#define NPAIR 128
#define TE 1536              // T*E = 256*6
#define TE4 384              // TE/4

// Scratch for second[i][j] (16384 floats). Device global (no allocs allowed).
__device__ float g_second[NPAIR * NPAIR];

// ---------------------------------------------------------------------------
// Kernel 1: EXACTLY the R1-proven streaming kernel (5.4 TB/s). Do not touch.
// second[i,j] = sum_{t,e} (yij[i,j,t,e] - yi[j,t,e])^2 / err[j,t,e]^2 / 15360
// grid = (j: 128, i_grp: 8), block = 256 threads (8 warps).
// ---------------------------------------------------------------------------
__global__ void __launch_bounds__(256)
second_kernel(const float* __restrict__ yij,
              const float* __restrict__ yi,
              const float* __restrict__ in1,
              float* __restrict__ out)
{
    __shared__ float4 w_s[TE4];
    __shared__ float4 y_s[TE4];

    const int j   = blockIdx.x;
    const int grp = blockIdx.y;
    const int tid = threadIdx.x;

    // Build weight tile w[j,t,e] = (1/15360) / err^2, and stage y_pred_i[j].
    const float scale = 1.0f / 15360.0f;   // 1/(T*E*10)
    float*  w_f = reinterpret_cast<float*>(w_s);
    float*  y_f = reinterpret_cast<float*>(y_s);
    #pragma unroll
    for (int idx = tid; idx < TE; idx += 256) {
        int t = idx / 6;
        int c = idx - t * 6;
        float e = in1[(j * 256 + t) * 15 + 7 + c];
        w_f[idx] = scale / (e * e);
        y_f[idx] = yi[j * TE + idx];
    }

    // Keep the (harmless) zero store to preserve R1 codegen exactly.
    if (j == 0 && grp == 0 && tid == 0) out[0] = 0.0f;

    __syncthreads();

    const int warp = tid >> 5;
    const int lane = tid & 31;
    const int i0   = grp * 16 + warp * 2;     // this warp's two i rows

    const float4* p0 = reinterpret_cast<const float4*>(
        yij + (size_t)(i0 * NPAIR + j) * TE);
    const float4* p1 = reinterpret_cast<const float4*>(
        yij + (size_t)((i0 + 1) * NPAIR + j) * TE);

    float a0 = 0.0f, a1 = 0.0f;
    #pragma unroll
    for (int k = 0; k < 12; ++k) {
        const int x = lane + 32 * k;
        const float4 wv = w_s[x];
        const float4 yv = y_s[x];
        const float4 g0 = p0[x];
        const float4 g1 = p1[x];
        float d;
        d = g0.x - yv.x; a0 = fmaf(d * d, wv.x, a0);
        d = g0.y - yv.y; a0 = fmaf(d * d, wv.y, a0);
        d = g0.z - yv.z; a0 = fmaf(d * d, wv.z, a0);
        d = g0.w - yv.w; a0 = fmaf(d * d, wv.w, a0);
        d = g1.x - yv.x; a1 = fmaf(d * d, wv.x, a1);
        d = g1.y - yv.y; a1 = fmaf(d * d, wv.y, a1);
        d = g1.z - yv.z; a1 = fmaf(d * d, wv.z, a1);
        d = g1.w - yv.w; a1 = fmaf(d * d, wv.w, a1);
    }

    #pragma unroll
    for (int o = 16; o; o >>= 1) {
        a0 += __shfl_xor_sync(0xFFFFFFFFu, a0, o);
        a1 += __shfl_xor_sync(0xFFFFFFFFu, a1, o);
    }
    if (lane == 0) {
        g_second[i0 * NPAIR + j]       = a0;
        g_second[(i0 + 1) * NPAIR + j] = a1;
    }
}

// ---------------------------------------------------------------------------
// Kernel 2: single block, 1024 threads (32 warps).
// L_sim = mean_{i,j} | S_ij - 0.5*(second[i,j] + second[j,i]) |
// Thread (jj = tid&127, grp8 = tid>>7) handles 16 values of i.
// g_second is 64 KB, L2-resident; writes out[0] directly (no atomics).
// ---------------------------------------------------------------------------
__global__ void __launch_bounds__(1024)
final_kernel(const float* __restrict__ samples,
             float* __restrict__ out)
{
    __shared__ float smp[1280];     // samples (128 x 10)
    __shared__ float s_part[32];

    const int tid = threadIdx.x;
    for (int x = tid; x < 1280; x += 1024) smp[x] = samples[x];
    __syncthreads();

    const int jj   = tid & 127;
    const int grp8 = tid >> 7;      // 0..7, each covers 16 i's
    float sj[10];
    #pragma unroll
    for (int d = 0; d < 10; ++d) sj[d] = smp[jj * 10 + d];

    float acc = 0.0f;
    const int ibeg = grp8 * 16;
    #pragma unroll
    for (int q = 0; q < 16; ++q) {
        const int i = ibeg + q;
        float S = 0.0f;
        #pragma unroll
        for (int d = 0; d < 10; ++d) {
            float df = smp[i * 10 + d] - sj[d];
            S = fmaf(df, df, S);
        }
        float sA = g_second[i * NPAIR + jj];   // coalesced across jj
        float sB = g_second[jj * NPAIR + i];   // transposed, L2-resident
        acc += fabsf(S * 0.1f - 0.5f * (sA + sB));
    }

    #pragma unroll
    for (int o = 16; o; o >>= 1)
        acc += __shfl_xor_sync(0xFFFFFFFFu, acc, o);
    if ((tid & 31) == 0) s_part[tid >> 5] = acc;
    __syncthreads();

    if (tid < 32) {
        float v = s_part[tid];
        #pragma unroll
        for (int o = 16; o; o >>= 1)
            v += __shfl_xor_sync(0xFFFFFFFFu, v, o);
        if (tid == 0) out[0] = v * (1.0f / 16384.0f);
    }
}

// ---------------------------------------------------------------------------
extern "C" void kernel_launch(void* const* d_in, const int* in_sizes, int n_in,
                              void* d_out, int out_size)
{
    (void)in_sizes; (void)n_in; (void)out_size;
    const float* yi      = (const float*)d_in[1];
    const float* yij     = (const float*)d_in[2];
    const float* in1     = (const float*)d_in[3];
    const float* samples = (const float*)d_in[4];
    float* out = (float*)d_out;

    dim3 grid1(NPAIR, 8);
    second_kernel<<<grid1, 256>>>(yij, yi, in1, out);
    final_kernel<<<1, 1024>>>(samples, out);
}

// round 5
// speedup vs baseline: 1.5368x; 1.3071x over previous
#include <cuda_runtime.h>
#include <cstdint>

// Shapes: N=128, T=256, E=6, D=10
//   merged   : (128,256,14)  fp32  -- UNUSED
//   y_pred_i : (128,256,6)   fp32
//   y_pred_ij: (128,128,256,6) fp32  (dominant: ~100.7 MB, streamed once)
//   input1   : (128,256,15)  fp32  (err_true = cols 7..12)
//   samples  : (128,10)      fp32
//   labels   : (128,)        int64 -- UNUSED
// Output: scalar fp32 L_sim.

#define NPAIR 128
#define TE 1536              // T*E = 256*6
#define TE4 384              // TE/4

// second[i][j] stored twice: row-major and transposed, so kernel 2 reads
// both operands coalesced (the transposed read was costing 15 us on one SM).
__device__ float g_second [NPAIR * NPAIR];
__device__ float g_secondT[NPAIR * NPAIR];

// ---------------------------------------------------------------------------
// Kernel 1: R1-proven streaming kernel (5.4 TB/s) + one extra transposed
// store in the lane-0 epilogue (after the hot loop; does not perturb it).
// second[i,j] = sum_{t,e} (yij[i,j,t,e] - yi[j,t,e])^2 / err[j,t,e]^2 / 15360
// grid = (j: 128, i_grp: 8), block = 256 threads (8 warps).
// ---------------------------------------------------------------------------
__global__ void __launch_bounds__(256)
second_kernel(const float* __restrict__ yij,
              const float* __restrict__ yi,
              const float* __restrict__ in1,
              float* __restrict__ out)
{
    __shared__ float4 w_s[TE4];
    __shared__ float4 y_s[TE4];

    const int j   = blockIdx.x;
    const int grp = blockIdx.y;
    const int tid = threadIdx.x;

    // Build weight tile w[j,t,e] = (1/15360) / err^2, and stage y_pred_i[j].
    const float scale = 1.0f / 15360.0f;   // 1/(T*E*10)
    float*  w_f = reinterpret_cast<float*>(w_s);
    float*  y_f = reinterpret_cast<float*>(y_s);
    #pragma unroll
    for (int idx = tid; idx < TE; idx += 256) {
        int t = idx / 6;
        int c = idx - t * 6;
        float e = in1[(j * 256 + t) * 15 + 7 + c];
        w_f[idx] = scale / (e * e);
        y_f[idx] = yi[j * TE + idx];
    }

    // Zero the scalar output (kernel 2 accumulates into it via atomicAdd).
    if (j == 0 && grp == 0 && tid == 0) out[0] = 0.0f;

    __syncthreads();

    const int warp = tid >> 5;
    const int lane = tid & 31;
    const int i0   = grp * 16 + warp * 2;     // this warp's two i rows

    const float4* p0 = reinterpret_cast<const float4*>(
        yij + (size_t)(i0 * NPAIR + j) * TE);
    const float4* p1 = reinterpret_cast<const float4*>(
        yij + (size_t)((i0 + 1) * NPAIR + j) * TE);

    float a0 = 0.0f, a1 = 0.0f;
    #pragma unroll
    for (int k = 0; k < 12; ++k) {
        const int x = lane + 32 * k;
        const float4 wv = w_s[x];
        const float4 yv = y_s[x];
        const float4 g0 = p0[x];
        const float4 g1 = p1[x];
        float d;
        d = g0.x - yv.x; a0 = fmaf(d * d, wv.x, a0);
        d = g0.y - yv.y; a0 = fmaf(d * d, wv.y, a0);
        d = g0.z - yv.z; a0 = fmaf(d * d, wv.z, a0);
        d = g0.w - yv.w; a0 = fmaf(d * d, wv.w, a0);
        d = g1.x - yv.x; a1 = fmaf(d * d, wv.x, a1);
        d = g1.y - yv.y; a1 = fmaf(d * d, wv.y, a1);
        d = g1.z - yv.z; a1 = fmaf(d * d, wv.z, a1);
        d = g1.w - yv.w; a1 = fmaf(d * d, wv.w, a1);
    }

    #pragma unroll
    for (int o = 16; o; o >>= 1) {
        a0 += __shfl_xor_sync(0xFFFFFFFFu, a0, o);
        a1 += __shfl_xor_sync(0xFFFFFFFFu, a1, o);
    }
    if (lane == 0) {
        g_second [i0 * NPAIR + j]        = a0;
        g_second [(i0 + 1) * NPAIR + j]  = a1;
        g_secondT[j * NPAIR + i0]        = a0;   // transposed copy
        g_secondT[j * NPAIR + i0 + 1]    = a1;
    }
}

// ---------------------------------------------------------------------------
// Kernel 2: grid = 8 blocks x 256 threads.
// L_sim = mean_{i,j} | S_ij - 0.5*(second[i,j] + second[j,i]) |
// Thread (jj = tid&127, half = tid>>7) handles 8 i values:
//   i in [blockIdx.x*16 + half*8, +8).
// Both g_second and g_secondT reads are coalesced across jj (L2-resident).
// One atomicAdd per block into out (zeroed by kernel 1).
// ---------------------------------------------------------------------------
__global__ void __launch_bounds__(256)
final_kernel(const float* __restrict__ samples,
             float* __restrict__ out)
{
    __shared__ float smp[1280];     // samples (128 x 10)
    __shared__ float s_part[8];

    const int tid = threadIdx.x;
    for (int x = tid; x < 1280; x += 256) smp[x] = samples[x];
    __syncthreads();

    const int jj   = tid & 127;
    const int half = tid >> 7;
    const int ibeg = blockIdx.x * 16 + half * 8;

    float sj[10];
    #pragma unroll
    for (int d = 0; d < 10; ++d) sj[d] = smp[jj * 10 + d];

    float acc = 0.0f;
    #pragma unroll
    for (int q = 0; q < 8; ++q) {
        const int i = ibeg + q;
        float S = 0.0f;
        #pragma unroll
        for (int d = 0; d < 10; ++d) {
            float df = smp[i * 10 + d] - sj[d];
            S = fmaf(df, df, S);
        }
        float sA = g_second [i * NPAIR + jj];   // second[i, jj]  (coalesced)
        float sB = g_secondT[i * NPAIR + jj];   // second[jj, i]  (coalesced)
        acc += fabsf(S * 0.1f - 0.5f * (sA + sB));
    }

    #pragma unroll
    for (int o = 16; o; o >>= 1)
        acc += __shfl_xor_sync(0xFFFFFFFFu, acc, o);
    if ((tid & 31) == 0) s_part[tid >> 5] = acc;
    __syncthreads();

    if (tid == 0) {
        float s = 0.0f;
        #pragma unroll
        for (int w = 0; w < 8; ++w) s += s_part[w];
        atomicAdd(out, s * (1.0f / 16384.0f));
    }
}

// ---------------------------------------------------------------------------
extern "C" void kernel_launch(void* const* d_in, const int* in_sizes, int n_in,
                              void* d_out, int out_size)
{
    (void)in_sizes; (void)n_in; (void)out_size;
    const float* yi      = (const float*)d_in[1];
    const float* yij     = (const float*)d_in[2];
    const float* in1     = (const float*)d_in[3];
    const float* samples = (const float*)d_in[4];
    float* out = (float*)d_out;

    dim3 grid1(NPAIR, 8);
    second_kernel<<<grid1, 256>>>(yij, yi, in1, out);
    final_kernel<<<8, 256>>>(samples, out);
}